// round 15
// baseline (speedup 1.0000x reference)
#include <cuda_runtime.h>
#include <cuda_bf16.h>
#include <cuda_fp16.h>

// ---------------- static scratch (no allocations allowed) ----------------
#define N_MAX   65536
#define ET_MAX  2097152   // E + N capacity
#define SCAN_B  512

__device__ __align__(16) int   g_rowptr[N_MAX + 1];
__device__ __align__(16) int   g_fill[N_MAX];
__device__ __align__(16) int   g_colsrc[ET_MAX];
__device__ int g_desc[128];                                  // lookback descriptors
__device__ __align__(16) __half g_acth[(size_t)N_MAX * 128]; // layer-1 activations (fp16)
__device__ __align__(16) __half g_hb[(size_t)N_MAX * 128];   // layer-2 GEMM output (fp16)
__device__ __align__(16) float4 g_as[N_MAX];                 // layer-2 alpha_src (4 heads)
__device__ __align__(16) float4 g_ad[N_MAX];                 // layer-2 alpha_dst
__device__ __align__(16) float g_h3[N_MAX];
__device__ int g_is64;

// ---------------- helpers ----------------
__device__ __forceinline__ float leakyf(float x) { return x > 0.f ? x : 0.2f * x; }
__device__ __forceinline__ float eluf(float x)   { return x > 0.f ? x : (__expf(x) - 1.f); }

__device__ __forceinline__ float selh(float4 v, int h) {
    return h == 0 ? v.x : (h == 1 ? v.y : (h == 2 ? v.z : v.w));
}
__device__ __forceinline__ void red4(float4& v) {
#pragma unroll
    for (int o = 16; o; o >>= 1) {
        v.x += __shfl_xor_sync(0xffffffffu, v.x, o);
        v.y += __shfl_xor_sync(0xffffffffu, v.y, o);
        v.z += __shfl_xor_sync(0xffffffffu, v.z, o);
        v.w += __shfl_xor_sync(0xffffffffu, v.w, o);
    }
}
__device__ __forceinline__ int edge_val(const void* ei, long long idx, int is64) {
    if (is64) return (int)((const long long*)ei)[idx];
    return ((const int*)ei)[idx];
}

// ---------------- CSR build ----------------
__global__ void k_zero(const void* ei, int E, int N, int Etot) {
    int i = blockIdx.x * blockDim.x + threadIdx.x;
    if (i < N) g_fill[i] = 0;
    if (i < 128) g_desc[i] = 0;
    if (i == 0) g_rowptr[N] = Etot;
    if (blockIdx.x == 0) {
        __shared__ int bad;
        if (threadIdx.x == 0) bad = 0;
        __syncthreads();
        int n = E < 64 ? E : 64;
        if ((int)threadIdx.x < n && ((const int*)ei)[2 * threadIdx.x + 1] != 0) bad = 1;
        __syncthreads();
        if (threadIdx.x == 0) g_is64 = !bad;
    }
}

__global__ void k_hist(const void* ei, int E) {
    int i0 = (blockIdx.x * blockDim.x + threadIdx.x) * 2;
    int is64 = g_is64;
    if (i0 < E) {
        int d = edge_val(ei, (long long)E + i0, is64);
        atomicAdd(&g_fill[d], 1);
    }
    if (i0 + 1 < E) {
        int d = edge_val(ei, (long long)E + i0 + 1, is64);
        atomicAdd(&g_fill[d], 1);
    }
}

// single-pass scan with decoupled lookback: rowptr/fill = exclusive prefix of (count+1)
__global__ void k_scan(int N) {
    __shared__ int wsum[16];
    __shared__ int s_excl;
    int t = threadIdx.x, b = blockIdx.x;
    int lane = t & 31, wp = t >> 5;
    int i = b * SCAN_B + t;
    int v = (i < N) ? g_fill[i] + 1 : 0;
    int x = v;
#pragma unroll
    for (int o = 1; o < 32; o <<= 1) {
        int u = __shfl_up_sync(0xffffffffu, x, o);
        if (lane >= o) x += u;
    }
    if (lane == 31) wsum[wp] = x;
    __syncthreads();
    if (wp == 0) {
        int y = (lane < 16) ? wsum[lane] : 0;
#pragma unroll
        for (int o = 1; o < 16; o <<= 1) {
            int u = __shfl_up_sync(0xffffffffu, y, o);
            if (lane >= o) y += u;
        }
        if (lane < 16) wsum[lane] = y;
    }
    __syncthreads();
    int incl = x + (wp ? wsum[wp - 1] : 0);
    int agg = wsum[15];
    if (t == 0) {
        if (b == 0) {
            atomicExch(&g_desc[0], agg | (2 << 30));
            s_excl = 0;
        } else {
            atomicExch(&g_desc[b], agg | (1 << 30));
            int excl = 0, idx = b - 1;
            while (true) {
                int d = atomicAdd(&g_desc[idx], 0);
                unsigned st = (unsigned)d >> 30;
                if (st == 2u) { excl += d & 0x3FFFFFFF; break; }
                if (st == 1u) { excl += d & 0x3FFFFFFF; idx--; }
            }
            __threadfence();
            atomicExch(&g_desc[b], (excl + agg) | (2 << 30));
            s_excl = excl;
        }
    }
    __syncthreads();
    int ex = s_excl + incl - v;
    if (i < N) {
        g_rowptr[i] = ex;
        g_fill[i] = ex;
    }
}

__global__ void k_scatter(const void* ei, int E, int N) {
    int i = blockIdx.x * blockDim.x + threadIdx.x;
    int tot = E + N;
    if (i >= tot) return;
    int is64 = g_is64;
    int s, d;
    if (i < E) {
        s = edge_val(ei, i, is64);
        d = edge_val(ei, (long long)E + i, is64);
    } else {
        s = i - E; d = s;
    }
    int pos = atomicAdd(&g_fill[d], 1);
    g_colsrc[pos] = s;
}

// ---------------- layer 1 (act1 stored fp16) ----------------
__global__ void k_agg1(const float* __restrict__ x, const float* __restrict__ W1,
                       const float* __restrict__ as1, const float* __restrict__ ad1,
                       const float* __restrict__ b1, int N) {
    __shared__ float sw[8];   // ws[0..3], wd[0..3]
    int t = threadIdx.x;
    if (t < 8) {
        int h = t & 3;
        const float* av = (t < 4) ? as1 : ad1;
        float s = 0.f;
#pragma unroll
        for (int c = 0; c < 32; c++) s += W1[h * 32 + c] * av[h * 32 + c];
        sw[t] = s;
    }
    __syncthreads();
    int wid = (blockIdx.x * blockDim.x + t) >> 5;
    int lane = t & 31;
    if (wid >= N) return;
    float4 ws = *(const float4*)&sw[0];
    float4 wd = *(const float4*)&sw[4];
    float xd = __ldg(&x[wid]);
    float4 ad = make_float4(xd * wd.x, xd * wd.y, xd * wd.z, xd * wd.w);
    int lo = g_rowptr[wid], hi = g_rowptr[wid + 1];
    float4 tt = make_float4(0, 0, 0, 0);
    float4 ss = make_float4(0, 0, 0, 0);
    for (int i = lo + lane; i < hi; i += 32) {
        int s = g_colsrc[i];
        float xs = __ldg(&x[s]);
        float4 p;
        p.x = __expf(leakyf(xs * ws.x + ad.x));
        p.y = __expf(leakyf(xs * ws.y + ad.y));
        p.z = __expf(leakyf(xs * ws.z + ad.z));
        p.w = __expf(leakyf(xs * ws.w + ad.w));
        ss.x += p.x; ss.y += p.y; ss.z += p.z; ss.w += p.w;
        tt.x += p.x * xs; tt.y += p.y * xs; tt.z += p.z * xs; tt.w += p.w * xs;
    }
    red4(tt); red4(ss);
    int hd = lane >> 3;
    float th = selh(tt, hd) / selh(ss, hd);
    float4 w = *(const float4*)&W1[lane * 4];
    float4 b = *(const float4*)&b1[lane * 4];
    float4 o;
    o.x = eluf(th * w.x + b.x);
    o.y = eluf(th * w.y + b.y);
    o.z = eluf(th * w.z + b.z);
    o.w = eluf(th * w.w + b.w);
    __half2 h0 = __floats2half2_rn(o.x, o.y);
    __half2 h1 = __floats2half2_rn(o.z, o.w);
    uint2 u;
    u.x = *reinterpret_cast<unsigned*>(&h0);
    u.y = *reinterpret_cast<unsigned*>(&h1);
    *(uint2*)&g_acth[(size_t)wid * 128 + lane * 4] = u;
}

// ---------------- layer 2 GEMM: HMMA tensor cores (fp16 in, fp32 acc) ----------------
__device__ __forceinline__ void mma16816(float* c, const unsigned* a, const unsigned* b) {
    asm volatile(
        "mma.sync.aligned.m16n8k16.row.col.f32.f16.f16.f32 "
        "{%0,%1,%2,%3}, {%4,%5,%6,%7}, {%8,%9}, {%0,%1,%2,%3};"
        : "+f"(c[0]), "+f"(c[1]), "+f"(c[2]), "+f"(c[3])
        : "r"(a[0]), "r"(a[1]), "r"(a[2]), "r"(a[3]), "r"(b[0]), "r"(b[1]));
}

__global__ void k_gemm(const float* __restrict__ B,
                       const float* __restrict__ aw, const float* __restrict__ dw,
                       int N) {
    __shared__ __align__(16) unsigned char sm[49152];
    // [0,16384): A 64x128 fp16 swizzled; [16384,49152): B 128x128 fp16 swizzled
    // After mma: reused as Os 64x132 fp32
    float* Os = (float*)sm;
    int tid = threadIdx.x;
    int lane = tid & 31, w = tid >> 5;
    int row0 = blockIdx.x * 64;

    // fill A: 64 rows x 256 B = 1024 chunks of 16 B, 16 chunks per row
    for (int c = tid; c < 1024; c += 256) {
        int row = c >> 4, g = c & 15;
        uint4 v = *(const uint4*)&g_acth[(size_t)(row0 + row) * 128 + g * 8];
        unsigned off = (unsigned)(row * 256 + g * 16) ^ ((row & 7) << 4);
        *(uint4*)(sm + off) = v;
    }
    // fill B (fp32 -> fp16): 128 rows x 256 B = 2048 chunks of 16 B
    for (int c = tid; c < 2048; c += 256) {
        int k = c >> 4, n8 = (c & 15) * 8;
        float4 f0 = *(const float4*)&B[k * 128 + n8];
        float4 f1 = *(const float4*)&B[k * 128 + n8 + 4];
        __half2 q0 = __floats2half2_rn(f0.x, f0.y);
        __half2 q1 = __floats2half2_rn(f0.z, f0.w);
        __half2 q2 = __floats2half2_rn(f1.x, f1.y);
        __half2 q3 = __floats2half2_rn(f1.z, f1.w);
        uint4 u;
        u.x = *reinterpret_cast<unsigned*>(&q0);
        u.y = *reinterpret_cast<unsigned*>(&q1);
        u.z = *reinterpret_cast<unsigned*>(&q2);
        u.w = *reinterpret_cast<unsigned*>(&q3);
        unsigned off = (unsigned)(k * 256 + n8 * 2) ^ ((k & 7) << 4);
        *(uint4*)(sm + 16384 + off) = u;
    }
    __syncthreads();

    unsigned sbase = (unsigned)__cvta_generic_to_shared(sm);
    int wr = (w >> 1) * 16;      // warp row tile (0..48)
    int wc = (w & 1) * 64;       // warp col tile (0 or 64)
    float acc[8][4];
#pragma unroll
    for (int i = 0; i < 8; i++)
#pragma unroll
        for (int j = 0; j < 4; j++) acc[i][j] = 0.f;

    int rowA = wr + (lane & 7) + ((lane >> 3) & 1) * 8;
    int tb = lane & 15;
#pragma unroll
    for (int ks = 0; ks < 8; ks++) {
        int k0 = ks * 16;
        int ka = k0 + ((lane >> 4) & 1) * 8;
        unsigned offA = (unsigned)(rowA * 256 + ka * 2) ^ ((rowA & 7) << 4);
        unsigned a[4];
        asm volatile("ldmatrix.sync.aligned.m8n8.x4.shared.b16 {%0,%1,%2,%3}, [%4];"
                     : "=r"(a[0]), "=r"(a[1]), "=r"(a[2]), "=r"(a[3])
                     : "r"(sbase + offA));
        int kb = k0 + tb;
#pragma unroll
        for (int nt = 0; nt < 8; nt++) {
            int n0 = wc + nt * 8;
            unsigned offB = ((unsigned)(kb * 256 + n0 * 2) ^ ((kb & 7) << 4)) + 16384;
            unsigned b[2];
            asm volatile("ldmatrix.sync.aligned.m8n8.x2.trans.shared.b16 {%0,%1}, [%2];"
                         : "=r"(b[0]), "=r"(b[1])
                         : "r"(sbase + offB));
            mma16816(acc[nt], a, b);
        }
    }
    __syncthreads();   // all mma smem reads done before Os overwrite

    // scatter acc into Os (64 x 132 fp32)
    {
        int r0_ = wr + (lane >> 2);
        int cb = (lane & 3) * 2;
#pragma unroll
        for (int nt = 0; nt < 8; nt++) {
            int col = wc + nt * 8 + cb;
            Os[r0_ * 132 + col]       = acc[nt][0];
            Os[r0_ * 132 + col + 1]   = acc[nt][1];
            Os[(r0_ + 8) * 132 + col]     = acc[nt][2];
            Os[(r0_ + 8) * 132 + col + 1] = acc[nt][3];
        }
    }
    __syncthreads();

    // output phase: warp w handles rows w*8 .. w*8+7
    float4 wa = *(const float4*)&aw[lane * 4];
    float4 wd4 = *(const float4*)&dw[lane * 4];
#pragma unroll
    for (int rr = 0; rr < 8; rr++) {
        int lrow = w * 8 + rr;
        int row = row0 + lrow;
        float4 v = *(const float4*)&Os[lrow * 132 + lane * 4];
        if (row < N) {
            __half2 h0 = __floats2half2_rn(v.x, v.y);
            __half2 h1 = __floats2half2_rn(v.z, v.w);
            uint2 u;
            u.x = *reinterpret_cast<unsigned*>(&h0);
            u.y = *reinterpret_cast<unsigned*>(&h1);
            *(uint2*)&g_hb[(size_t)row * 128 + lane * 4] = u;
        }
        float pa = v.x * wa.x + v.y * wa.y + v.z * wa.z + v.w * wa.w;
        float pd = v.x * wd4.x + v.y * wd4.y + v.z * wd4.z + v.w * wd4.w;
#pragma unroll
        for (int o = 4; o; o >>= 1) {
            pa += __shfl_xor_sync(0xffffffffu, pa, o);
            pd += __shfl_xor_sync(0xffffffffu, pd, o);
        }
        float a0 = __shfl_sync(0xffffffffu, pa, 0);
        float a1 = __shfl_sync(0xffffffffu, pa, 8);
        float a2v = __shfl_sync(0xffffffffu, pa, 16);
        float a3 = __shfl_sync(0xffffffffu, pa, 24);
        float d0 = __shfl_sync(0xffffffffu, pd, 0);
        float d1 = __shfl_sync(0xffffffffu, pd, 8);
        float d2 = __shfl_sync(0xffffffffu, pd, 16);
        float d3 = __shfl_sync(0xffffffffu, pd, 24);
        if (lane == 0 && row < N) {
            g_as[row] = make_float4(a0, a1, a2v, a3);
            g_ad[row] = make_float4(d0, d1, d2, d3);
        }
    }
}

// ---------------- layer 2 aggregation (fp16 gather) + fused layer-3 projection ----------------
#define AGG2_WARPS 8
__global__ void k_agg2(const float* __restrict__ b2, const float* __restrict__ W3,
                       int N) {
    __shared__ float shp[AGG2_WARPS][4][33];   // p transposed [head][slot]
    __shared__ int   shs[AGG2_WARPS][32];
    int w = threadIdx.x >> 5, lane = threadIdx.x & 31;
    int n = blockIdx.x * AGG2_WARPS + w;
    if (n >= N) return;
    int lo = g_rowptr[n], hi = g_rowptr[n + 1];
    float4 ad = g_ad[n];
    float4 ss = make_float4(0, 0, 0, 0);
    float4 acc = make_float4(0, 0, 0, 0);
    int hd = lane >> 3;
    const float* prow = &shp[w][hd][0];
    for (int base = lo; base < hi; base += 32) {
        int i = base + lane;
        if (i < hi) {
            int s = g_colsrc[i];
            float4 as = g_as[s];
            float4 p;
            p.x = __expf(leakyf(as.x + ad.x));
            p.y = __expf(leakyf(as.y + ad.y));
            p.z = __expf(leakyf(as.z + ad.z));
            p.w = __expf(leakyf(as.w + ad.w));
            ss.x += p.x; ss.y += p.y; ss.z += p.z; ss.w += p.w;
            shp[w][0][lane] = p.x;
            shp[w][1][lane] = p.y;
            shp[w][2][lane] = p.z;
            shp[w][3][lane] = p.w;
            shs[w][lane] = s;
        }
        __syncwarp();
        int cnt = hi - base; if (cnt > 32) cnt = 32;
#pragma unroll 4
        for (int j = 0; j < cnt; j++) {
            int s = shs[w][j];
            float ph = prow[j];
            uint2 u = *(const uint2*)&g_hb[(size_t)s * 128 + lane * 4];
            __half2 h0 = *reinterpret_cast<__half2*>(&u.x);
            __half2 h1 = *reinterpret_cast<__half2*>(&u.y);
            float2 f0 = __half22float2(h0);
            float2 f1 = __half22float2(h1);
            acc.x += ph * f0.x; acc.y += ph * f0.y;
            acc.z += ph * f1.x; acc.w += ph * f1.y;
        }
        __syncwarp();
    }
    red4(ss);
    float inv = 1.f / selh(ss, hd);
    float4 b = *(const float4*)&b2[lane * 4];
    float4 o;
    o.x = eluf(acc.x * inv + b.x);
    o.y = eluf(acc.y * inv + b.y);
    o.z = eluf(acc.z * inv + b.z);
    o.w = eluf(acc.w * inv + b.w);
    float4 w3 = *(const float4*)&W3[lane * 4];
    float part = o.x * w3.x + o.y * w3.y + o.z * w3.z + o.w * w3.w;
#pragma unroll
    for (int off = 16; off; off >>= 1) part += __shfl_xor_sync(0xffffffffu, part, off);
    if (lane == 0) g_h3[n] = part;
}

// ---------------- layer 3 aggregation ----------------
__global__ void k_agg3(const float* __restrict__ a3s, const float* __restrict__ a3d,
                       const float* __restrict__ b3, float* __restrict__ out, int N) {
    int n = (blockIdx.x * blockDim.x + threadIdx.x) >> 5;
    int lane = threadIdx.x & 31;
    if (n >= N) return;
    float sa = __ldg(a3s), sd = __ldg(a3d);
    int lo = g_rowptr[n], hi = g_rowptr[n + 1];
    float adn = g_h3[n] * sd;
    float num = 0.f, den = 0.f;
    for (int i = lo + lane; i < hi; i += 32) {
        int s = g_colsrc[i];
        float h3s = g_h3[s];
        float p = __expf(leakyf(h3s * sa + adn));
        num += p * h3s;
        den += p;
    }
#pragma unroll
    for (int o = 16; o; o >>= 1) {
        num += __shfl_xor_sync(0xffffffffu, num, o);
        den += __shfl_xor_sync(0xffffffffu, den, o);
    }
    if (lane == 0) out[n] = num / den + __ldg(b3);
}

// ---------------- launch ----------------
extern "C" void kernel_launch(void* const* d_in, const int* in_sizes, int n_in,
                              void* d_out, int out_size) {
    const float* x   = (const float*)d_in[0];
    const void*  ei  = d_in[1];
    const float* W1  = (const float*)d_in[2];
    const float* as1 = (const float*)d_in[3];
    const float* ad1 = (const float*)d_in[4];
    const float* b1  = (const float*)d_in[5];
    const float* W2  = (const float*)d_in[6];
    const float* as2 = (const float*)d_in[7];
    const float* ad2 = (const float*)d_in[8];
    const float* b2  = (const float*)d_in[9];
    const float* W3  = (const float*)d_in[10];
    const float* a3s = (const float*)d_in[11];
    const float* a3d = (const float*)d_in[12];
    const float* b3  = (const float*)d_in[13];
    float* out = (float*)d_out;

    int N = in_sizes[0];            // IN_C = 1
    int E = in_sizes[1] / 2;        // element count is 2E for both int32/int64
    int Etot = E + N;
    int nb = (N + SCAN_B - 1) / SCAN_B;

    // CSR build (4 kernels)
    k_zero<<<(N + 255) / 256, 256>>>(ei, E, N, Etot);
    k_hist<<<(E / 2 + 256) / 256, 256>>>(ei, E);
    k_scan<<<nb, SCAN_B>>>(N);
    k_scatter<<<(Etot + 255) / 256, 256>>>(ei, E, N);

    // layer 1 (act1 stored fp16)
    k_agg1<<<(N + 7) / 8, 256>>>(x, W1, as1, ad1, b1, N);

    // layer 2 (tensor-core GEMM, alpha2 fused)
    k_gemm<<<(N + 63) / 64, 256>>>(W2, as2, ad2, N);
    k_agg2<<<(N + AGG2_WARPS - 1) / AGG2_WARPS, AGG2_WARPS * 32>>>(b2, W3, N);

    // layer 3 (alphas inline)
    k_agg3<<<(N + 7) / 8, 256>>>(a3s, a3d, b3, out, N);
}

// round 16
// speedup vs baseline: 1.0563x; 1.0563x over previous
#include <cuda_runtime.h>
#include <cuda_bf16.h>
#include <cuda_fp16.h>

// ---------------- static scratch (no allocations allowed) ----------------
#define N_MAX   65536
#define ET_MAX  2097152   // E + N capacity
#define SCAN_B  512

__device__ __align__(16) int   g_rowptr[N_MAX + 1];
__device__ __align__(16) int   g_fill[N_MAX];
__device__ __align__(16) int   g_colsrc[ET_MAX];
__device__ __align__(16) int   g_bsum[256];
__device__ __align__(16) __half g_acth[(size_t)N_MAX * 128]; // layer-1 activations (fp16)
__device__ __align__(16) __half g_hb[(size_t)N_MAX * 128];   // layer-2 GEMM output (fp16)
__device__ __align__(16) float4 g_as[N_MAX];                 // layer-2 alpha_src (4 heads)
__device__ __align__(16) float4 g_ad[N_MAX];                 // layer-2 alpha_dst
__device__ __align__(16) float g_h3[N_MAX];
__device__ int g_is64;

// ---------------- helpers ----------------
__device__ __forceinline__ float leakyf(float x) { return x > 0.f ? x : 0.2f * x; }
__device__ __forceinline__ float eluf(float x)   { return x > 0.f ? x : (__expf(x) - 1.f); }

__device__ __forceinline__ float selh(float4 v, int h) {
    return h == 0 ? v.x : (h == 1 ? v.y : (h == 2 ? v.z : v.w));
}
__device__ __forceinline__ void red4(float4& v) {
#pragma unroll
    for (int o = 16; o; o >>= 1) {
        v.x += __shfl_xor_sync(0xffffffffu, v.x, o);
        v.y += __shfl_xor_sync(0xffffffffu, v.y, o);
        v.z += __shfl_xor_sync(0xffffffffu, v.z, o);
        v.w += __shfl_xor_sync(0xffffffffu, v.w, o);
    }
}
__device__ __forceinline__ int edge_val(const void* ei, long long idx, int is64) {
    if (is64) return (int)((const long long*)ei)[idx];
    return ((const int*)ei)[idx];
}

// ---------------- CSR build ----------------
__global__ void k_zero(const void* ei, int E, int N, int Etot) {
    int i = blockIdx.x * blockDim.x + threadIdx.x;
    if (i < N) g_fill[i] = 0;
    if (i == 0) g_rowptr[N] = Etot;
    if (blockIdx.x == 0) {
        __shared__ int bad;
        if (threadIdx.x == 0) bad = 0;
        __syncthreads();
        int n = E < 64 ? E : 64;
        if ((int)threadIdx.x < n && ((const int*)ei)[2 * threadIdx.x + 1] != 0) bad = 1;
        __syncthreads();
        if (threadIdx.x == 0) g_is64 = !bad;
    }
}

__global__ void k_hist(const void* ei, int E) {
    int i0 = (blockIdx.x * blockDim.x + threadIdx.x) * 2;
    int is64 = g_is64;
    if (i0 < E) {
        int d = edge_val(ei, (long long)E + i0, is64);
        atomicAdd(&g_fill[d], 1);
    }
    if (i0 + 1 < E) {
        int d = edge_val(ei, (long long)E + i0 + 1, is64);
        atomicAdd(&g_fill[d], 1);
    }
}

__global__ void k_scanA(int N) {
    __shared__ int sh[SCAN_B];
    int t = threadIdx.x;
    int i = blockIdx.x * SCAN_B + t;
    sh[t] = (i < N) ? g_fill[i] + 1 : 0;
    __syncthreads();
#pragma unroll
    for (int o = SCAN_B / 2; o > 0; o >>= 1) {
        if (t < o) sh[t] += sh[t + o];
        __syncthreads();
    }
    if (t == 0) g_bsum[blockIdx.x] = sh[0];
}

// block-local exclusive scan + self-computed block offset.
// Also writes each node's SELF-LOOP into the last slot of its row
// (softmax aggregation is order-independent), so k_scatter handles edges only.
__global__ void k_scanC(int N, int nb) {
    __shared__ int sh[SCAN_B];
    __shared__ int pre[128];
    int t = threadIdx.x;
    int b = blockIdx.x;
    if (t < 128) pre[t] = (t < nb && t < b) ? g_bsum[t] : 0;
    __syncthreads();
#pragma unroll
    for (int o = 64; o > 0; o >>= 1) {
        if (t < o) pre[t] += pre[t + o];
        __syncthreads();
    }
    int boff = pre[0];
    int i = b * SCAN_B + t;
    int v = (i < N) ? g_fill[i] + 1 : 0;
    sh[t] = v;
    __syncthreads();
#pragma unroll
    for (int o = 1; o < SCAN_B; o <<= 1) {
        int u = (t >= o) ? sh[t - o] : 0;
        __syncthreads();
        sh[t] += u;
        __syncthreads();
    }
    if (i < N) {
        int ex = sh[t] - v + boff;
        g_rowptr[i] = ex;
        g_fill[i] = ex;
        g_colsrc[ex + v - 1] = i;   // self-loop in last slot of row
    }
}

// edges only; 4 per thread, grid-strided so each unroll step is coalesced
__global__ void k_scatter(const void* ei, int E) {
    int T = gridDim.x * blockDim.x;
    int t0 = blockIdx.x * blockDim.x + threadIdx.x;
    int is64 = g_is64;
#pragma unroll
    for (int q = 0; q < 4; q++) {
        int i = t0 + q * T;
        if (i < E) {
            int s = edge_val(ei, i, is64);
            int d = edge_val(ei, (long long)E + i, is64);
            int pos = atomicAdd(&g_fill[d], 1);
            g_colsrc[pos] = s;
        }
    }
}

// ---------------- layer 1 (act1 stored fp16) ----------------
__global__ void k_agg1(const float* __restrict__ x, const float* __restrict__ W1,
                       const float* __restrict__ as1, const float* __restrict__ ad1,
                       const float* __restrict__ b1, int N) {
    __shared__ float sw[8];   // ws[0..3], wd[0..3]
    int t = threadIdx.x;
    if (t < 8) {
        int h = t & 3;
        const float* av = (t < 4) ? as1 : ad1;
        float s = 0.f;
#pragma unroll
        for (int c = 0; c < 32; c++) s += W1[h * 32 + c] * av[h * 32 + c];
        sw[t] = s;
    }
    __syncthreads();
    int wid = (blockIdx.x * blockDim.x + t) >> 5;
    int lane = t & 31;
    if (wid >= N) return;
    float4 ws = *(const float4*)&sw[0];
    float4 wd = *(const float4*)&sw[4];
    float xd = __ldg(&x[wid]);
    float4 ad = make_float4(xd * wd.x, xd * wd.y, xd * wd.z, xd * wd.w);
    int lo = g_rowptr[wid], hi = g_rowptr[wid + 1];
    float4 tt = make_float4(0, 0, 0, 0);
    float4 ss = make_float4(0, 0, 0, 0);
    for (int i = lo + lane; i < hi; i += 32) {
        int s = g_colsrc[i];
        float xs = __ldg(&x[s]);
        float4 p;
        p.x = __expf(leakyf(xs * ws.x + ad.x));
        p.y = __expf(leakyf(xs * ws.y + ad.y));
        p.z = __expf(leakyf(xs * ws.z + ad.z));
        p.w = __expf(leakyf(xs * ws.w + ad.w));
        ss.x += p.x; ss.y += p.y; ss.z += p.z; ss.w += p.w;
        tt.x += p.x * xs; tt.y += p.y * xs; tt.z += p.z * xs; tt.w += p.w * xs;
    }
    red4(tt); red4(ss);
    int hd = lane >> 3;
    float th = selh(tt, hd) / selh(ss, hd);
    float4 w = *(const float4*)&W1[lane * 4];
    float4 b = *(const float4*)&b1[lane * 4];
    float4 o;
    o.x = eluf(th * w.x + b.x);
    o.y = eluf(th * w.y + b.y);
    o.z = eluf(th * w.z + b.z);
    o.w = eluf(th * w.w + b.w);
    __half2 h0 = __floats2half2_rn(o.x, o.y);
    __half2 h1 = __floats2half2_rn(o.z, o.w);
    uint2 u;
    u.x = *reinterpret_cast<unsigned*>(&h0);
    u.y = *reinterpret_cast<unsigned*>(&h1);
    *(uint2*)&g_acth[(size_t)wid * 128 + lane * 4] = u;
}

// ---------------- layer 2 GEMM: HMMA tensor cores (fp16 in, fp32 acc) ----------------
__device__ __forceinline__ void mma16816(float* c, const unsigned* a, const unsigned* b) {
    asm volatile(
        "mma.sync.aligned.m16n8k16.row.col.f32.f16.f16.f32 "
        "{%0,%1,%2,%3}, {%4,%5,%6,%7}, {%8,%9}, {%0,%1,%2,%3};"
        : "+f"(c[0]), "+f"(c[1]), "+f"(c[2]), "+f"(c[3])
        : "r"(a[0]), "r"(a[1]), "r"(a[2]), "r"(a[3]), "r"(b[0]), "r"(b[1]));
}

__global__ void k_gemm(const float* __restrict__ B,
                       const float* __restrict__ aw, const float* __restrict__ dw,
                       int N) {
    __shared__ __align__(16) unsigned char sm[49152];
    float* Os = (float*)sm;
    int tid = threadIdx.x;
    int lane = tid & 31, w = tid >> 5;
    int row0 = blockIdx.x * 64;

    // fill A: 64 rows x 256 B = 1024 chunks of 16 B, 16 chunks per row
    for (int c = tid; c < 1024; c += 256) {
        int row = c >> 4, g = c & 15;
        uint4 v = *(const uint4*)&g_acth[(size_t)(row0 + row) * 128 + g * 8];
        unsigned off = (unsigned)(row * 256 + g * 16) ^ ((row & 7) << 4);
        *(uint4*)(sm + off) = v;
    }
    // fill B (fp32 -> fp16): 128 rows x 256 B = 2048 chunks of 16 B
    for (int c = tid; c < 2048; c += 256) {
        int k = c >> 4, n8 = (c & 15) * 8;
        float4 f0 = *(const float4*)&B[k * 128 + n8];
        float4 f1 = *(const float4*)&B[k * 128 + n8 + 4];
        __half2 q0 = __floats2half2_rn(f0.x, f0.y);
        __half2 q1 = __floats2half2_rn(f0.z, f0.w);
        __half2 q2 = __floats2half2_rn(f1.x, f1.y);
        __half2 q3 = __floats2half2_rn(f1.z, f1.w);
        uint4 u;
        u.x = *reinterpret_cast<unsigned*>(&q0);
        u.y = *reinterpret_cast<unsigned*>(&q1);
        u.z = *reinterpret_cast<unsigned*>(&q2);
        u.w = *reinterpret_cast<unsigned*>(&q3);
        unsigned off = (unsigned)(k * 256 + n8 * 2) ^ ((k & 7) << 4);
        *(uint4*)(sm + 16384 + off) = u;
    }
    __syncthreads();

    unsigned sbase = (unsigned)__cvta_generic_to_shared(sm);
    int wr = (w >> 1) * 16;
    int wc = (w & 1) * 64;
    float acc[8][4];
#pragma unroll
    for (int i = 0; i < 8; i++)
#pragma unroll
        for (int j = 0; j < 4; j++) acc[i][j] = 0.f;

    int rowA = wr + (lane & 7) + ((lane >> 3) & 1) * 8;
    int tb = lane & 15;
#pragma unroll
    for (int ks = 0; ks < 8; ks++) {
        int k0 = ks * 16;
        int ka = k0 + ((lane >> 4) & 1) * 8;
        unsigned offA = (unsigned)(rowA * 256 + ka * 2) ^ ((rowA & 7) << 4);
        unsigned a[4];
        asm volatile("ldmatrix.sync.aligned.m8n8.x4.shared.b16 {%0,%1,%2,%3}, [%4];"
                     : "=r"(a[0]), "=r"(a[1]), "=r"(a[2]), "=r"(a[3])
                     : "r"(sbase + offA));
        int kb = k0 + tb;
#pragma unroll
        for (int nt = 0; nt < 8; nt++) {
            int n0 = wc + nt * 8;
            unsigned offB = ((unsigned)(kb * 256 + n0 * 2) ^ ((kb & 7) << 4)) + 16384;
            unsigned b[2];
            asm volatile("ldmatrix.sync.aligned.m8n8.x2.trans.shared.b16 {%0,%1}, [%2];"
                         : "=r"(b[0]), "=r"(b[1])
                         : "r"(sbase + offB));
            mma16816(acc[nt], a, b);
        }
    }
    __syncthreads();

    // scatter acc into Os (64 x 132 fp32)
    {
        int r0_ = wr + (lane >> 2);
        int cb = (lane & 3) * 2;
#pragma unroll
        for (int nt = 0; nt < 8; nt++) {
            int col = wc + nt * 8 + cb;
            Os[r0_ * 132 + col]       = acc[nt][0];
            Os[r0_ * 132 + col + 1]   = acc[nt][1];
            Os[(r0_ + 8) * 132 + col]     = acc[nt][2];
            Os[(r0_ + 8) * 132 + col + 1] = acc[nt][3];
        }
    }
    __syncthreads();

    // output phase: warp w handles rows w*8 .. w*8+7
    float4 wa = *(const float4*)&aw[lane * 4];
    float4 wd4 = *(const float4*)&dw[lane * 4];
#pragma unroll
    for (int rr = 0; rr < 8; rr++) {
        int lrow = w * 8 + rr;
        int row = row0 + lrow;
        float4 v = *(const float4*)&Os[lrow * 132 + lane * 4];
        if (row < N) {
            __half2 h0 = __floats2half2_rn(v.x, v.y);
            __half2 h1 = __floats2half2_rn(v.z, v.w);
            uint2 u;
            u.x = *reinterpret_cast<unsigned*>(&h0);
            u.y = *reinterpret_cast<unsigned*>(&h1);
            *(uint2*)&g_hb[(size_t)row * 128 + lane * 4] = u;
        }
        float pa = v.x * wa.x + v.y * wa.y + v.z * wa.z + v.w * wa.w;
        float pd = v.x * wd4.x + v.y * wd4.y + v.z * wd4.z + v.w * wd4.w;
#pragma unroll
        for (int o = 4; o; o >>= 1) {
            pa += __shfl_xor_sync(0xffffffffu, pa, o);
            pd += __shfl_xor_sync(0xffffffffu, pd, o);
        }
        float a0 = __shfl_sync(0xffffffffu, pa, 0);
        float a1 = __shfl_sync(0xffffffffu, pa, 8);
        float a2v = __shfl_sync(0xffffffffu, pa, 16);
        float a3 = __shfl_sync(0xffffffffu, pa, 24);
        float d0 = __shfl_sync(0xffffffffu, pd, 0);
        float d1 = __shfl_sync(0xffffffffu, pd, 8);
        float d2 = __shfl_sync(0xffffffffu, pd, 16);
        float d3 = __shfl_sync(0xffffffffu, pd, 24);
        if (lane == 0 && row < N) {
            g_as[row] = make_float4(a0, a1, a2v, a3);
            g_ad[row] = make_float4(d0, d1, d2, d3);
        }
    }
}

// ---------------- layer 2 aggregation (fp16 gather) + fused layer-3 projection ----------------
#define AGG2_WARPS 8
__global__ void k_agg2(const float* __restrict__ b2, const float* __restrict__ W3,
                       int N) {
    __shared__ float shp[AGG2_WARPS][4][33];   // p transposed [head][slot]
    __shared__ int   shs[AGG2_WARPS][32];
    int w = threadIdx.x >> 5, lane = threadIdx.x & 31;
    int n = blockIdx.x * AGG2_WARPS + w;
    if (n >= N) return;
    int lo = g_rowptr[n], hi = g_rowptr[n + 1];
    float4 ad = g_ad[n];
    float4 ss = make_float4(0, 0, 0, 0);
    float4 acc = make_float4(0, 0, 0, 0);
    int hd = lane >> 3;
    const float* prow = &shp[w][hd][0];
    for (int base = lo; base < hi; base += 32) {
        int i = base + lane;
        if (i < hi) {
            int s = g_colsrc[i];
            float4 as = g_as[s];
            float4 p;
            p.x = __expf(leakyf(as.x + ad.x));
            p.y = __expf(leakyf(as.y + ad.y));
            p.z = __expf(leakyf(as.z + ad.z));
            p.w = __expf(leakyf(as.w + ad.w));
            ss.x += p.x; ss.y += p.y; ss.z += p.z; ss.w += p.w;
            shp[w][0][lane] = p.x;
            shp[w][1][lane] = p.y;
            shp[w][2][lane] = p.z;
            shp[w][3][lane] = p.w;
            shs[w][lane] = s;
        }
        __syncwarp();
        int cnt = hi - base; if (cnt > 32) cnt = 32;
#pragma unroll 4
        for (int j = 0; j < cnt; j++) {
            int s = shs[w][j];
            float ph = prow[j];
            uint2 u = *(const uint2*)&g_hb[(size_t)s * 128 + lane * 4];
            __half2 h0 = *reinterpret_cast<__half2*>(&u.x);
            __half2 h1 = *reinterpret_cast<__half2*>(&u.y);
            float2 f0 = __half22float2(h0);
            float2 f1 = __half22float2(h1);
            acc.x += ph * f0.x; acc.y += ph * f0.y;
            acc.z += ph * f1.x; acc.w += ph * f1.y;
        }
        __syncwarp();
    }
    red4(ss);
    float inv = 1.f / selh(ss, hd);
    float4 b = *(const float4*)&b2[lane * 4];
    float4 o;
    o.x = eluf(acc.x * inv + b.x);
    o.y = eluf(acc.y * inv + b.y);
    o.z = eluf(acc.z * inv + b.z);
    o.w = eluf(acc.w * inv + b.w);
    float4 w3 = *(const float4*)&W3[lane * 4];
    float part = o.x * w3.x + o.y * w3.y + o.z * w3.z + o.w * w3.w;
#pragma unroll
    for (int off = 16; off; off >>= 1) part += __shfl_xor_sync(0xffffffffu, part, off);
    if (lane == 0) g_h3[n] = part;
}

// ---------------- layer 3 aggregation ----------------
__global__ void k_agg3(const float* __restrict__ a3s, const float* __restrict__ a3d,
                       const float* __restrict__ b3, float* __restrict__ out, int N) {
    int n = (blockIdx.x * blockDim.x + threadIdx.x) >> 5;
    int lane = threadIdx.x & 31;
    if (n >= N) return;
    float sa = __ldg(a3s), sd = __ldg(a3d);
    int lo = g_rowptr[n], hi = g_rowptr[n + 1];
    float adn = g_h3[n] * sd;
    float num = 0.f, den = 0.f;
    for (int i = lo + lane; i < hi; i += 32) {
        int s = g_colsrc[i];
        float h3s = g_h3[s];
        float p = __expf(leakyf(h3s * sa + adn));
        num += p * h3s;
        den += p;
    }
#pragma unroll
    for (int o = 16; o; o >>= 1) {
        num += __shfl_xor_sync(0xffffffffu, num, o);
        den += __shfl_xor_sync(0xffffffffu, den, o);
    }
    if (lane == 0) out[n] = num / den + __ldg(b3);
}

// ---------------- launch ----------------
extern "C" void kernel_launch(void* const* d_in, const int* in_sizes, int n_in,
                              void* d_out, int out_size) {
    const float* x   = (const float*)d_in[0];
    const void*  ei  = d_in[1];
    const float* W1  = (const float*)d_in[2];
    const float* as1 = (const float*)d_in[3];
    const float* ad1 = (const float*)d_in[4];
    const float* b1  = (const float*)d_in[5];
    const float* W2  = (const float*)d_in[6];
    const float* as2 = (const float*)d_in[7];
    const float* ad2 = (const float*)d_in[8];
    const float* b2  = (const float*)d_in[9];
    const float* W3  = (const float*)d_in[10];
    const float* a3s = (const float*)d_in[11];
    const float* a3d = (const float*)d_in[12];
    const float* b3  = (const float*)d_in[13];
    float* out = (float*)d_out;

    int N = in_sizes[0];            // IN_C = 1
    int E = in_sizes[1] / 2;        // element count is 2E for both int32/int64
    int Etot = E + N;
    int nb = (N + SCAN_B - 1) / SCAN_B;

    // CSR build
    k_zero<<<(N + 255) / 256, 256>>>(ei, E, N, Etot);
    k_hist<<<(E / 2 + 256) / 256, 256>>>(ei, E);
    k_scanA<<<nb, SCAN_B>>>(N);
    k_scanC<<<nb, SCAN_B>>>(N, nb);
    k_scatter<<<(E / 4 + 256) / 256, 256>>>(ei, E);

    // layer 1 (act1 stored fp16)
    k_agg1<<<(N + 7) / 8, 256>>>(x, W1, as1, ad1, b1, N);

    // layer 2 (tensor-core GEMM, alpha2 fused)
    k_gemm<<<(N + 63) / 64, 256>>>(W2, as2, ad2, N);
    k_agg2<<<(N + AGG2_WARPS - 1) / AGG2_WARPS, AGG2_WARPS * 32>>>(b2, W3, N);

    // layer 3 (alphas inline)
    k_agg3<<<(N + 7) / 8, 256>>>(a3s, a3d, b3, out, N);
}